// round 9
// baseline (speedup 1.0000x reference)
#include <cuda_runtime.h>

#define INDIM   256
#define OUTDIM  256
#define BATCH   128
#define NK      12                  // dense slots per input: 11 coef + 1 residual
#define KS      16                  // k-splits over inputs
#define IPC     (INDIM / KS)        // 16 inputs per chunk
#define KCH     (IPC * NK)          // 192 dense k per chunk
#define OT      32                  // output cols per block
#define TBB     64                  // batch rows per block
#define VSTR    33                  // padded s_V row stride (conflict-free)
#define NTHR    256

#define SMEM_V2 (KCH * VSTR)                    // 6336 u64  (50688 B)
#define SMEM_W  (KCH * TBB)                     // 12288 f32 (49152 B)
#define DYN_SMEM (SMEM_V2 * 8 + SMEM_W * 4)     // 99840 B -> 2 blocks/SM

__device__ float g_part[KS * BATCH * OUTDIM];   // 2 MB split-K partials

__device__ __forceinline__ unsigned long long pack2(float v)
{
    unsigned long long p;
    asm("mov.b64 %0, {%1, %1};" : "=l"(p) : "r"(__float_as_uint(v)));
    return p;
}

// ---- Kernel 1: fused fold + closed-form basis + split-K GEMM ----------------
__global__ __launch_bounds__(NTHR)
void kan_gemm(const float* __restrict__ x,
              const float* __restrict__ coef,
              const float* __restrict__ rw,
              const float* __restrict__ uw)
{
    extern __shared__ __align__(16) unsigned long long dyn[];
    unsigned long long* s_V2 = dyn;                    // [k][o_l] f32x2-duplicated
    float*              s_W  = (float*)(dyn + SMEM_V2); // [k][b_l] stride TBB

    __shared__ float s_u[OT * IPC];  // uw tile [o_l*16 + i_l]

    const int o0 = blockIdx.x * OT;
    const int b0 = blockIdx.y * TBB;
    const int ks = blockIdx.z;
    const int i0 = ks * IPC;
    const int t  = threadIdx.x;

    // ---- phase 1: stage uw, drop rw into s_V slot 11, zero s_W --------------
    #pragma unroll
    for (int q = t; q < OT * IPC; q += NTHR) {
        const int o_l = q >> 4, i_l = q & 15;
        const int gi = (o0 + o_l) * INDIM + i0 + i_l;
        s_u[q] = uw[gi];
        s_V2[(i_l * NK + 11) * VSTR + o_l] = pack2(rw[gi]);
    }
    {
        float4* sw4 = (float4*)s_W;
        const float4 z = make_float4(0.f, 0.f, 0.f, 0.f);
        #pragma unroll
        for (int q = t; q < SMEM_W / 4; q += NTHR) sw4[q] = z;   // 12 STS.128
    }
    __syncthreads();

    // ---- phase 2a: fold coef * uw -> s_V2 (coalesced LDG, conflict-free STS)
    #pragma unroll
    for (int idx = t; idx < OT * IPC * 11; idx += NTHR) {
        const int o_l = idx / 176;               // 176 = 16 i * 11 k
        const int rem = idx - o_l * 176;
        const int i_l = rem / 11;
        const int kk  = rem - i_l * 11;
        const float c = coef[(size_t)(o0 + o_l) * (INDIM * 11) + (i0 + i_l) * 11 + kk];
        s_V2[(i_l * NK + kk) * VSTR + o_l] = pack2(s_u[o_l * IPC + i_l] * c);
    }

    // ---- phase 2b: closed-form uniform cubic basis, scatter into zeroed s_W
    // knots: g[q] = -1.75 + 0.25 q  ->  u = 4x + 7, j = floor(u) in [3,10]
    {
        const int b_l  = t & 63;
        const int part = t >> 6;                 // 0..3
        const float4 xv4 = *(const float4*)(x + (b0 + b_l) * INDIM + i0 + part * 4);

        #pragma unroll
        for (int s = 0; s < 4; ++s) {
            const float xv = (s == 0) ? xv4.x : (s == 1) ? xv4.y
                           : (s == 2) ? xv4.z : xv4.w;
            float u  = fmaf(xv, 4.0f, 7.0f);
            float fj = floorf(u);
            fj = fminf(fmaxf(fj, 3.0f), 10.0f);
            const float tt = u - fj;             // [0,1)
            const int   j  = (int)fj;

            const float omt  = 1.0f - tt;
            const float t2   = tt * tt;
            const float t3   = t2 * tt;
            const float k6   = 1.0f / 6.0f;
            const float w0 = omt * omt * omt * k6;                       // (1-t)^3/6
            const float w1 = fmaf(0.5f, t3, fmaf(-1.0f, t2, 4.0f * k6)); // (3t^3-6t^2+4)/6
            const float w2 = fmaf(0.5f, t2 + tt - t3, k6);               // (-3t^3+3t^2+3t+1)/6
            const float w3 = t3 * k6;                                    // t^3/6
            const float si = xv / (1.0f + __expf(-xv));                  // silu

            const int i_l = part * 4 + s;
            float* wb = &s_W[(i_l * NK) * TBB + b_l];
            const int idx = j - 3;               // 0..7
            wb[(idx    ) * TBB] = w0;            // bank = b_l -> conflict-free scatter
            wb[(idx + 1) * TBB] = w1;
            wb[(idx + 2) * TBB] = w2;
            wb[(idx + 3) * TBB] = w3;
            wb[ 11       * TBB] = si;
        }
    }
    __syncthreads();

    // ---- main loop: thread = (o_l, bg); 8 b-rows as 4 packed f32x2 accums ---
    const int o_l = t & 31;
    const int bg  = t >> 5;                      // 0..7, constant per warp
    const int bb  = bg * 8;

    unsigned long long acc2[4] = {0ull, 0ull, 0ull, 0ull};

    #pragma unroll 4
    for (int k = 0; k < KCH; ++k) {
        const unsigned long long v2 = s_V2[k * VSTR + o_l];            // LDS.64
        const ulonglong2* wp = (const ulonglong2*)&s_W[k * TBB + bb];  // 32B-aligned
        ulonglong2 w01 = wp[0];                  // LDS.128 broadcast
        ulonglong2 w23 = wp[1];
        asm("fma.rn.f32x2 %0, %1, %2, %0;" : "+l"(acc2[0]) : "l"(w01.x), "l"(v2));
        asm("fma.rn.f32x2 %0, %1, %2, %0;" : "+l"(acc2[1]) : "l"(w01.y), "l"(v2));
        asm("fma.rn.f32x2 %0, %1, %2, %0;" : "+l"(acc2[2]) : "l"(w23.x), "l"(v2));
        asm("fma.rn.f32x2 %0, %1, %2, %0;" : "+l"(acc2[3]) : "l"(w23.y), "l"(v2));
    }

    float* pp = g_part + ((size_t)ks * BATCH + b0 + bb) * OUTDIM + o0 + o_l;
    #pragma unroll
    for (int j = 0; j < 4; ++j) {
        unsigned int lo, hi;
        asm("mov.b64 {%0, %1}, %2;" : "=r"(lo), "=r"(hi) : "l"(acc2[j]));
        pp[(2 * j)     * OUTDIM] = __uint_as_float(lo);   // coalesced over o_l
        pp[(2 * j + 1) * OUTDIM] = __uint_as_float(hi);
    }

    cudaTriggerProgrammaticLaunchCompletion();   // let reduce spin up under our tail
}

// ---- Kernel 2: reduce split-K partials (PDL consumer) -----------------------
__global__ __launch_bounds__(256)
void kan_reduce(float* __restrict__ out)
{
    cudaGridDependencySynchronize();             // all gemm stores visible
    const int idx = blockIdx.x * 256 + threadIdx.x;   // 32768 outputs
    float s = 0.0f;
    #pragma unroll
    for (int z = 0; z < KS; ++z)
        s += g_part[(size_t)z * (BATCH * OUTDIM) + idx];   // coalesced, MLP=16
    out[idx] = s;
}

// ------------------------------------------------------------------------------
extern "C" void kernel_launch(void* const* d_in, const int* in_sizes, int n_in,
                              void* d_out, int out_size)
{
    const float* x    = (const float*)d_in[0];
    const float* coef = (const float*)d_in[2];
    const float* rw   = (const float*)d_in[3];
    const float* uw   = (const float*)d_in[4];

    cudaFuncSetAttribute(kan_gemm, cudaFuncAttributeMaxDynamicSharedMemorySize, DYN_SMEM);

    kan_gemm<<<dim3(OUTDIM / OT, BATCH / TBB, KS), NTHR, DYN_SMEM>>>(x, coef, rw, uw);

    cudaLaunchConfig_t cfg = {};
    cfg.gridDim  = dim3((BATCH * OUTDIM) / 256);
    cfg.blockDim = dim3(256);
    cfg.dynamicSmemBytes = 0;
    cfg.stream = 0;
    cudaLaunchAttribute attr[1];
    attr[0].id = cudaLaunchAttributeProgrammaticStreamSerialization;
    attr[0].val.programmaticStreamSerializationAllowed = 1;
    cfg.attrs = attr;
    cfg.numAttrs = 1;
    cudaLaunchKernelEx(&cfg, kan_reduce, (float*)d_out);
}

// round 11
// speedup vs baseline: 1.0475x; 1.0475x over previous
#include <cuda_runtime.h>

#define INDIM   256
#define OUTDIM  256
#define BATCH   128
#define NK      12                  // dense slots per input: 11 coef + 1 residual
#define KS      16                  // k-splits over inputs
#define IPC     (INDIM / KS)        // 16 inputs per chunk
#define KCH     (IPC * NK)          // 192 dense k per chunk
#define OT      32                  // output cols per block
#define TBB     64                  // batch rows per block
#define VSTR    33                  // padded s_V row stride (conflict-free)
#define NTHR    256

#define SMEM_V2 (KCH * VSTR)                    // 6336 u64  (50688 B)
#define SMEM_W  (KCH * TBB)                     // 12288 f32 (49152 B)
#define DYN_SMEM (SMEM_V2 * 8 + SMEM_W * 4)     // 99840 B -> 2 blocks/SM

__device__ __forceinline__ unsigned long long pack2(float v)
{
    unsigned long long p;
    asm("mov.b64 %0, {%1, %1};" : "=l"(p) : "r"(__float_as_uint(v)));
    return p;
}

// ---- single fused kernel: fold + closed-form basis + split-K GEMM + REDG ----
__global__ __launch_bounds__(NTHR)
void kan_gemm(const float* __restrict__ x,
              const float* __restrict__ coef,
              const float* __restrict__ rw,
              const float* __restrict__ uw,
              float* __restrict__ out)
{
    extern __shared__ __align__(16) unsigned long long dyn[];
    unsigned long long* s_V2 = dyn;                      // [k][o_l] f32x2-duplicated
    float*              s_W  = (float*)(dyn + SMEM_V2);  // [k][b_l] stride TBB

    __shared__ float s_u[OT * IPC];  // uw tile [o_l*16 + i_l]

    const int o0 = blockIdx.x * OT;
    const int b0 = blockIdx.y * TBB;
    const int ks = blockIdx.z;
    const int i0 = ks * IPC;
    const int t  = threadIdx.x;

    // ---- phase 1: stage uw, drop rw into s_V slot 11, zero s_W --------------
    #pragma unroll
    for (int q = t; q < OT * IPC; q += NTHR) {
        const int o_l = q >> 4, i_l = q & 15;
        const int gi = (o0 + o_l) * INDIM + i0 + i_l;
        s_u[q] = uw[gi];
        s_V2[(i_l * NK + 11) * VSTR + o_l] = pack2(rw[gi]);
    }
    {
        float4* sw4 = (float4*)s_W;
        const float4 z = make_float4(0.f, 0.f, 0.f, 0.f);
        #pragma unroll
        for (int q = t; q < SMEM_W / 4; q += NTHR) sw4[q] = z;   // 12 STS.128
    }
    __syncthreads();

    // ---- phase 2a: fold coef * uw -> s_V2 (coalesced LDG, conflict-free STS)
    #pragma unroll
    for (int idx = t; idx < OT * IPC * 11; idx += NTHR) {
        const int o_l = idx / 176;               // 176 = 16 i * 11 k
        const int rem = idx - o_l * 176;
        const int i_l = rem / 11;
        const int kk  = rem - i_l * 11;
        const float c = coef[(size_t)(o0 + o_l) * (INDIM * 11) + (i0 + i_l) * 11 + kk];
        s_V2[(i_l * NK + kk) * VSTR + o_l] = pack2(s_u[o_l * IPC + i_l] * c);
    }

    // ---- phase 2b: closed-form uniform cubic basis, scatter into zeroed s_W
    // knots: g[q] = -1.75 + 0.25 q  ->  u = 4x + 7, j = floor(u) in [3,10]
    {
        const int b_l  = t & 63;
        const int part = t >> 6;                 // 0..3
        const float4 xv4 = *(const float4*)(x + (b0 + b_l) * INDIM + i0 + part * 4);

        #pragma unroll
        for (int s = 0; s < 4; ++s) {
            const float xv = (s == 0) ? xv4.x : (s == 1) ? xv4.y
                           : (s == 2) ? xv4.z : xv4.w;
            float u  = fmaf(xv, 4.0f, 7.0f);
            float fj = floorf(u);
            fj = fminf(fmaxf(fj, 3.0f), 10.0f);
            const float tt = u - fj;             // [0,1)
            const int   j  = (int)fj;

            const float omt = 1.0f - tt;
            const float t2  = tt * tt;
            const float t3  = t2 * tt;
            const float k6  = 1.0f / 6.0f;
            const float w0 = omt * omt * omt * k6;
            const float w1 = fmaf(0.5f, t3, fmaf(-1.0f, t2, 4.0f * k6));
            const float w2 = fmaf(0.5f, t2 + tt - t3, k6);
            const float w3 = t3 * k6;
            const float si = xv / (1.0f + __expf(-xv));   // silu

            const int i_l = part * 4 + s;
            float* wb = &s_W[(i_l * NK) * TBB + b_l];
            const int idx = j - 3;               // 0..7
            wb[(idx    ) * TBB] = w0;            // bank = b_l -> conflict-free scatter
            wb[(idx + 1) * TBB] = w1;
            wb[(idx + 2) * TBB] = w2;
            wb[(idx + 3) * TBB] = w3;
            wb[ 11       * TBB] = si;
        }
    }
    __syncthreads();

    // ---- main loop: thread = (o_l, bg); 8 b-rows as 4 packed f32x2 accums ---
    const int o_l = t & 31;
    const int bg  = t >> 5;                      // 0..7, constant per warp
    const int bb  = bg * 8;

    unsigned long long acc2[4] = {0ull, 0ull, 0ull, 0ull};

    #pragma unroll 4
    for (int k = 0; k < KCH; ++k) {
        const unsigned long long v2 = s_V2[k * VSTR + o_l];            // LDS.64
        const ulonglong2* wp = (const ulonglong2*)&s_W[k * TBB + bb];  // 32B-aligned
        ulonglong2 w01 = wp[0];                  // LDS.128 broadcast
        ulonglong2 w23 = wp[1];
        asm("fma.rn.f32x2 %0, %1, %2, %0;" : "+l"(acc2[0]) : "l"(w01.x), "l"(v2));
        asm("fma.rn.f32x2 %0, %1, %2, %0;" : "+l"(acc2[1]) : "l"(w01.y), "l"(v2));
        asm("fma.rn.f32x2 %0, %1, %2, %0;" : "+l"(acc2[2]) : "l"(w23.x), "l"(v2));
        asm("fma.rn.f32x2 %0, %1, %2, %0;" : "+l"(acc2[3]) : "l"(w23.y), "l"(v2));
    }

    // ---- split-K accumulate directly into out via no-return global atomics --
    float* __restrict__ pp = out + (size_t)(b0 + bb) * OUTDIM + o0 + o_l;
    #pragma unroll
    for (int j = 0; j < 4; ++j) {
        unsigned int lo, hi;
        asm("mov.b64 {%0, %1}, %2;" : "=r"(lo), "=r"(hi) : "l"(acc2[j]));
        asm volatile("red.global.add.f32 [%0], %1;"
                     :: "l"(pp + (size_t)(2 * j)     * OUTDIM), "f"(__uint_as_float(lo)) : "memory");
        asm volatile("red.global.add.f32 [%0], %1;"
                     :: "l"(pp + (size_t)(2 * j + 1) * OUTDIM), "f"(__uint_as_float(hi)) : "memory");
    }
}

// ------------------------------------------------------------------------------
extern "C" void kernel_launch(void* const* d_in, const int* in_sizes, int n_in,
                              void* d_out, int out_size)
{
    const float* x    = (const float*)d_in[0];
    const float* coef = (const float*)d_in[2];
    const float* rw   = (const float*)d_in[3];
    const float* uw   = (const float*)d_in[4];

    cudaFuncSetAttribute(kan_gemm, cudaFuncAttributeMaxDynamicSharedMemorySize, DYN_SMEM);

    // zero the accumulator (memset node in the captured graph, then one kernel)
    cudaMemsetAsync(d_out, 0, (size_t)out_size * sizeof(float), 0);

    kan_gemm<<<dim3(OUTDIM / OT, BATCH / TBB, KS), NTHR, DYN_SMEM>>>(
        x, coef, rw, uw, (float*)d_out);
}

// round 12
// speedup vs baseline: 1.1768x; 1.1234x over previous
#include <cuda_runtime.h>

#define INDIM   256
#define OUTDIM  256
#define BATCH   128
#define NK      12                  // dense slots per input: 11 coef + 1 residual
#define KS      16                  // k-splits over inputs
#define IPC     (INDIM / KS)        // 16 inputs per chunk
#define KCH     (IPC * NK)          // 192 dense k per chunk
#define OT      32                  // output cols per block
#define TBB     64                  // batch rows per block
#define VSTR    33                  // padded s_V row stride
#define NTHR    256

#define SMEM_V  (KCH * VSTR)                    // 6336 f32 (25344 B)
#define SMEM_W  (KCH * TBB)                     // 12288 f32 (49152 B)
#define DYN_SMEM ((SMEM_V + SMEM_W) * 4)        // 74496 B -> 3 blocks/SM

__device__ __forceinline__ unsigned long long pack2(float v)
{
    unsigned long long p;
    asm("mov.b64 %0, {%1, %1};" : "=l"(p) : "r"(__float_as_uint(v)));
    return p;
}

// ---- single fused kernel: fold + closed-form basis + split-K GEMM + REDG ----
__global__ __launch_bounds__(NTHR)
void kan_gemm(const float* __restrict__ x,
              const float* __restrict__ coef,
              const float* __restrict__ rw,
              const float* __restrict__ uw,
              float* __restrict__ out)
{
    extern __shared__ __align__(16) float dyn[];
    float* s_V = dyn;                // [k][o_l] stride VSTR, scalar
    float* s_W = dyn + SMEM_V;       // [k][b_l] stride TBB

    const int o0 = blockIdx.x * OT;
    const int b0 = blockIdx.y * TBB;
    const int ks = blockIdx.z;
    const int i0 = ks * IPC;
    const int t  = threadIdx.x;

    // ---- phase 0: zero s_W (scatter target) ---------------------------------
    {
        float4* sw4 = (float4*)s_W;
        const float4 z = make_float4(0.f, 0.f, 0.f, 0.f);
        #pragma unroll
        for (int q = t; q < SMEM_W / 4; q += NTHR) sw4[q] = z;   // 12 STS.128
    }

    // ---- phase 1: fold coef*uw and rw -> s_V (registers, no staging buffer) -
    // thread handles 2 (o_l,i_l) pairs; 11 consecutive coef floats per pair
    #pragma unroll
    for (int pp = 0; pp < 2; ++pp) {
        const int p   = t + pp * NTHR;           // 0..511
        const int o_l = p >> 4, i_l = p & 15;
        const int gi  = (o0 + o_l) * INDIM + i0 + i_l;
        const float u = uw[gi];
        const float r = rw[gi];
        const float* c = coef + (size_t)(o0 + o_l) * (INDIM * 11) + (i0 + i_l) * 11;
        float* vb = &s_V[(i_l * NK) * VSTR + o_l];
        #pragma unroll
        for (int kk = 0; kk < 11; ++kk)
            vb[kk * VSTR] = u * c[kk];           // ~2-way STS conflicts, one-time
        vb[11 * VSTR] = r;
    }

    // ---- phase 2: closed-form uniform cubic basis, scatter into zeroed s_W --
    // knots: g[q] = -1.75 + 0.25 q  ->  u = 4x + 7, j = floor(u) in [3,10]
    {
        const int b_l  = t & 63;
        const int part = t >> 6;                 // 0..3
        const float4 xv4 = *(const float4*)(x + (b0 + b_l) * INDIM + i0 + part * 4);

        __syncthreads();                         // s_W zeroing done before scatter

        #pragma unroll
        for (int s = 0; s < 4; ++s) {
            const float xv = (s == 0) ? xv4.x : (s == 1) ? xv4.y
                           : (s == 2) ? xv4.z : xv4.w;
            float u  = fmaf(xv, 4.0f, 7.0f);
            float fj = floorf(u);
            fj = fminf(fmaxf(fj, 3.0f), 10.0f);
            const float tt = u - fj;             // [0,1)
            const int   j  = (int)fj;

            const float omt = 1.0f - tt;
            const float t2  = tt * tt;
            const float t3  = t2 * tt;
            const float k6  = 1.0f / 6.0f;
            const float w0 = omt * omt * omt * k6;
            const float w1 = fmaf(0.5f, t3, fmaf(-1.0f, t2, 4.0f * k6));
            const float w2 = fmaf(0.5f, t2 + tt - t3, k6);
            const float w3 = t3 * k6;
            const float si = xv / (1.0f + __expf(-xv));   // silu

            const int i_l = part * 4 + s;
            float* wb = &s_W[(i_l * NK) * TBB + b_l];
            const int idx = j - 3;               // 0..7
            wb[(idx    ) * TBB] = w0;            // bank = b_l -> conflict-free scatter
            wb[(idx + 1) * TBB] = w1;
            wb[(idx + 2) * TBB] = w2;
            wb[(idx + 3) * TBB] = w3;
            wb[ 11       * TBB] = si;
        }
    }
    __syncthreads();

    // ---- main loop: thread = (o_l, bg); 8 b-rows as 4 packed f32x2 accums ---
    const int o_l = t & 31;
    const int bg  = t >> 5;                      // 0..7, constant per warp
    const int bb  = bg * 8;

    unsigned long long acc2[4] = {0ull, 0ull, 0ull, 0ull};

    #pragma unroll 4
    for (int k = 0; k < KCH; ++k) {
        const float v = s_V[k * VSTR + o_l];               // LDS.32, conflict-free
        const unsigned long long v2 = pack2(v);            // 1 ALU mov (pipe idle)
        const ulonglong2* wp = (const ulonglong2*)&s_W[k * TBB + bb];  // 32B-aligned
        ulonglong2 w01 = wp[0];                  // LDS.128 broadcast
        ulonglong2 w23 = wp[1];
        asm("fma.rn.f32x2 %0, %1, %2, %0;" : "+l"(acc2[0]) : "l"(w01.x), "l"(v2));
        asm("fma.rn.f32x2 %0, %1, %2, %0;" : "+l"(acc2[1]) : "l"(w01.y), "l"(v2));
        asm("fma.rn.f32x2 %0, %1, %2, %0;" : "+l"(acc2[2]) : "l"(w23.x), "l"(v2));
        asm("fma.rn.f32x2 %0, %1, %2, %0;" : "+l"(acc2[3]) : "l"(w23.y), "l"(v2));
    }

    // ---- split-K accumulate directly into out via no-return global atomics --
    float* __restrict__ pp = out + (size_t)(b0 + bb) * OUTDIM + o0 + o_l;
    #pragma unroll
    for (int j = 0; j < 4; ++j) {
        unsigned int lo, hi;
        asm("mov.b64 {%0, %1}, %2;" : "=r"(lo), "=r"(hi) : "l"(acc2[j]));
        asm volatile("red.global.add.f32 [%0], %1;"
                     :: "l"(pp + (size_t)(2 * j)     * OUTDIM), "f"(__uint_as_float(lo)) : "memory");
        asm volatile("red.global.add.f32 [%0], %1;"
                     :: "l"(pp + (size_t)(2 * j + 1) * OUTDIM), "f"(__uint_as_float(hi)) : "memory");
    }
}

// ------------------------------------------------------------------------------
extern "C" void kernel_launch(void* const* d_in, const int* in_sizes, int n_in,
                              void* d_out, int out_size)
{
    const float* x    = (const float*)d_in[0];
    const float* coef = (const float*)d_in[2];
    const float* rw   = (const float*)d_in[3];
    const float* uw   = (const float*)d_in[4];

    cudaFuncSetAttribute(kan_gemm, cudaFuncAttributeMaxDynamicSharedMemorySize, DYN_SMEM);

    // zero the accumulator (memset node in the captured graph, then one kernel)
    cudaMemsetAsync(d_out, 0, (size_t)out_size * sizeof(float), 0);

    kan_gemm<<<dim3(OUTDIM / OT, BATCH / TBB, KS), NTHR, DYN_SMEM>>>(
        x, coef, rw, uw, (float*)d_out);
}